// round 7
// baseline (speedup 1.0000x reference)
#include <cuda_runtime.h>
#include <cuda_bf16.h>
#include <math.h>

// ---------------------------------------------------------------------------
// Problem constants
//   xq: (1024, 8, 640)   xk/xv: (8, 1024, 640)   mask: (8, 1024) int32 (bool)
//   Wq/Wk/Wv/Wp: (640,640), biases (640)
//   out: (1024, 8, 640) fp32, attn_save: (8, 1024) fp32
// ---------------------------------------------------------------------------
#define NQ   1024
#define BB   8
#define MM   1024
#define CC   640
#define RR   (NQ * BB)          // 8192 flattened rows for projections
#define EPS_OT 0.05f
#define N_ITERS 100

// ---------------- static device scratch (allocation-free rule) -------------
__device__ float g_q  [RR * CC];
__device__ float g_k  [RR * CC];
__device__ float g_v  [RR * CC];
__device__ float g_x  [RR * CC];
__device__ float g_sim[(size_t)BB * MM * NQ];
__device__ float g_Kx [(size_t)BB * MM * NQ];
__device__ float g_a  [BB * MM];
__device__ float g_b  [BB * NQ];
__device__ float g_mu [BB * MM];

// ---------------------------------------------------------------------------
// Generic 128x128x8 fp32 tiled GEMM core pieces (NT: both operands row-major
// along the reduction dim). Each thread computes an 8x8 microtile split as
// (ty*4, 64+ty*4) x (tx*4, 64+tx*4) so LDS.128 reads are conflict-free.
// ---------------------------------------------------------------------------

// out[r, j] = sum_c A[r*640+c] * W[j*640+c] + bias[j]
__global__ __launch_bounds__(256) void gemm_proj(
    const float* __restrict__ A,
    const float* __restrict__ W,
    const float* __restrict__ bias,
    float* __restrict__ out)
{
    __shared__ float As[8][128];
    __shared__ float Bs[8][128];
    const int tid  = threadIdx.x;
    const int m0   = blockIdx.y * 128;
    const int n0   = blockIdx.x * 128;
    const int lrow = tid >> 1;
    const int lk   = (tid & 1) * 4;
    const float* Arow = A + (size_t)(m0 + lrow) * CC + lk;
    const float* Brow = W + (size_t)(n0 + lrow) * CC + lk;
    const int tx = tid & 15, ty = tid >> 4;
    const int ra = ty * 4;
    const int cb = tx * 4;

    float acc[8][8];
#pragma unroll
    for (int i = 0; i < 8; i++)
#pragma unroll
        for (int j = 0; j < 8; j++) acc[i][j] = 0.f;

    for (int k0 = 0; k0 < CC; k0 += 8) {
        float4 av = *(const float4*)(Arow + k0);
        float4 bv = *(const float4*)(Brow + k0);
        As[lk+0][lrow] = av.x; As[lk+1][lrow] = av.y;
        As[lk+2][lrow] = av.z; As[lk+3][lrow] = av.w;
        Bs[lk+0][lrow] = bv.x; Bs[lk+1][lrow] = bv.y;
        Bs[lk+2][lrow] = bv.z; Bs[lk+3][lrow] = bv.w;
        __syncthreads();
#pragma unroll
        for (int kk = 0; kk < 8; kk++) {
            float4 a0 = *(const float4*)&As[kk][ra];
            float4 a1 = *(const float4*)&As[kk][ra + 64];
            float4 b0 = *(const float4*)&Bs[kk][cb];
            float4 b1 = *(const float4*)&Bs[kk][cb + 64];
            float ar[8] = {a0.x,a0.y,a0.z,a0.w,a1.x,a1.y,a1.z,a1.w};
            float br[8] = {b0.x,b0.y,b0.z,b0.w,b1.x,b1.y,b1.z,b1.w};
#pragma unroll
            for (int i = 0; i < 8; i++)
#pragma unroll
                for (int j = 0; j < 8; j++)
                    acc[i][j] += ar[i] * br[j];
        }
        __syncthreads();
    }

#pragma unroll
    for (int i = 0; i < 8; i++) {
        int m = m0 + ((i < 4) ? (ra + i) : (64 + ra + i - 4));
#pragma unroll
        for (int jh = 0; jh < 2; jh++) {
            int n = n0 + cb + jh * 64;
            float4 bia = *(const float4*)(bias + n);
            float4 o;
            o.x = acc[i][jh*4+0] + bia.x;
            o.y = acc[i][jh*4+1] + bia.y;
            o.z = acc[i][jh*4+2] + bia.z;
            o.w = acc[i][jh*4+3] + bia.w;
            *(float4*)(out + (size_t)m * CC + n) = o;
        }
    }
}

// sim[b,m,n] = sum_c k[b,m,c] * q[n,b,c];  Kx = exp((sim-1)/eps)
__global__ __launch_bounds__(256) void gemm_sim(
    const float* __restrict__ kb,
    const float* __restrict__ qb,
    float* __restrict__ sim,
    float* __restrict__ Kx)
{
    __shared__ float As[8][128];
    __shared__ float Bs[8][128];
    const int b    = blockIdx.z;
    const int tid  = threadIdx.x;
    const int m0   = blockIdx.y * 128;   // m tile
    const int n0   = blockIdx.x * 128;   // n tile
    const int lrow = tid >> 1;
    const int lk   = (tid & 1) * 4;
    const float* Arow = kb + ((size_t)b * MM + m0 + lrow) * CC + lk;
    const float* Brow = qb + (size_t)b * CC + (size_t)(n0 + lrow) * (BB * CC) + lk;
    const int tx = tid & 15, ty = tid >> 4;
    const int ra = ty * 4;
    const int cb = tx * 4;

    float acc[8][8];
#pragma unroll
    for (int i = 0; i < 8; i++)
#pragma unroll
        for (int j = 0; j < 8; j++) acc[i][j] = 0.f;

    for (int k0 = 0; k0 < CC; k0 += 8) {
        float4 av = *(const float4*)(Arow + k0);
        float4 bv = *(const float4*)(Brow + k0);
        As[lk+0][lrow] = av.x; As[lk+1][lrow] = av.y;
        As[lk+2][lrow] = av.z; As[lk+3][lrow] = av.w;
        Bs[lk+0][lrow] = bv.x; Bs[lk+1][lrow] = bv.y;
        Bs[lk+2][lrow] = bv.z; Bs[lk+3][lrow] = bv.w;
        __syncthreads();
#pragma unroll
        for (int kk = 0; kk < 8; kk++) {
            float4 a0 = *(const float4*)&As[kk][ra];
            float4 a1 = *(const float4*)&As[kk][ra + 64];
            float4 b0 = *(const float4*)&Bs[kk][cb];
            float4 b1 = *(const float4*)&Bs[kk][cb + 64];
            float ar[8] = {a0.x,a0.y,a0.z,a0.w,a1.x,a1.y,a1.z,a1.w};
            float br[8] = {b0.x,b0.y,b0.z,b0.w,b1.x,b1.y,b1.z,b1.w};
#pragma unroll
            for (int i = 0; i < 8; i++)
#pragma unroll
                for (int j = 0; j < 8; j++)
                    acc[i][j] += ar[i] * br[j];
        }
        __syncthreads();
    }

#pragma unroll
    for (int i = 0; i < 8; i++) {
        int m = m0 + ((i < 4) ? (ra + i) : (64 + ra + i - 4));
#pragma unroll
        for (int jh = 0; jh < 2; jh++) {
            int n = n0 + cb + jh * 64;
            size_t off = ((size_t)b * MM + m) * NQ + n;
            float4 s;
            s.x = acc[i][jh*4+0]; s.y = acc[i][jh*4+1];
            s.z = acc[i][jh*4+2]; s.w = acc[i][jh*4+3];
            *(float4*)(sim + off) = s;
            float4 kx;
            kx.x = expf((s.x - 1.0f) / EPS_OT);
            kx.y = expf((s.y - 1.0f) / EPS_OT);
            kx.z = expf((s.z - 1.0f) / EPS_OT);
            kx.w = expf((s.w - 1.0f) / EPS_OT);
            *(float4*)(Kx + off) = kx;
        }
    }
}

// x[n,b,c] = b[n] * sum_m (a[m]*Kx[b,m,n]) * v[b,m,c]
__global__ __launch_bounds__(256) void gemm_x(
    const float* __restrict__ Kx,
    const float* __restrict__ v,
    const float* __restrict__ a,
    const float* __restrict__ bvec,
    float* __restrict__ x)
{
    __shared__ float As[8][128];   // [m][n]
    __shared__ float Bs[8][128];   // [m][c]
    const int b   = blockIdx.z;
    const int tid = threadIdx.x;
    const int nO0 = blockIdx.y * 128;   // output rows (n)
    const int c0  = blockIdx.x * 128;   // output cols (c)
    const int km   = tid >> 5;          // 0..7
    const int off4 = (tid & 31) * 4;
    const int tx = tid & 15, ty = tid >> 4;
    const int ra = ty * 4;
    const int cb = tx * 4;

    float acc[8][8];
#pragma unroll
    for (int i = 0; i < 8; i++)
#pragma unroll
        for (int j = 0; j < 8; j++) acc[i][j] = 0.f;

    for (int m0 = 0; m0 < MM; m0 += 8) {
        float am = a[b * MM + m0 + km];
        float4 kv = *(const float4*)(Kx + ((size_t)b * MM + m0 + km) * NQ + nO0 + off4);
        float4 vv = *(const float4*)(v  + ((size_t)b * MM + m0 + km) * CC + c0  + off4);
        *(float4*)&As[km][off4] = make_float4(kv.x*am, kv.y*am, kv.z*am, kv.w*am);
        *(float4*)&Bs[km][off4] = vv;
        __syncthreads();
#pragma unroll
        for (int kk = 0; kk < 8; kk++) {
            float4 a0 = *(const float4*)&As[kk][ra];
            float4 a1 = *(const float4*)&As[kk][ra + 64];
            float4 b0 = *(const float4*)&Bs[kk][cb];
            float4 b1 = *(const float4*)&Bs[kk][cb + 64];
            float ar[8] = {a0.x,a0.y,a0.z,a0.w,a1.x,a1.y,a1.z,a1.w};
            float br[8] = {b0.x,b0.y,b0.z,b0.w,b1.x,b1.y,b1.z,b1.w};
#pragma unroll
            for (int i = 0; i < 8; i++)
#pragma unroll
                for (int j = 0; j < 8; j++)
                    acc[i][j] += ar[i] * br[j];
        }
        __syncthreads();
    }

#pragma unroll
    for (int i = 0; i < 8; i++) {
        int n = nO0 + ((i < 4) ? (ra + i) : (64 + ra + i - 4));
        float bn = bvec[b * NQ + n];
#pragma unroll
        for (int jh = 0; jh < 2; jh++) {
            int c = c0 + cb + jh * 64;
            float4 o;
            o.x = acc[i][jh*4+0] * bn;
            o.y = acc[i][jh*4+1] * bn;
            o.z = acc[i][jh*4+2] * bn;
            o.w = acc[i][jh*4+3] * bn;
            *(float4*)(x + ((size_t)n * BB + b) * CC + c) = o;
        }
    }
}

// ---------------------------------------------------------------------------
// l2norm over each 640-element row, in place. One warp per row.
// ---------------------------------------------------------------------------
__global__ __launch_bounds__(256) void l2norm_rows(float* __restrict__ buf)
{
    const int row  = blockIdx.x * 8 + (threadIdx.x >> 5);
    const int lane = threadIdx.x & 31;
    float4* p = (float4*)(buf + (size_t)row * CC);   // 160 float4
    float4 vals[5];
    float ss = 0.f;
#pragma unroll
    for (int i = 0; i < 5; i++) {
        vals[i] = p[lane + i * 32];
        ss += vals[i].x*vals[i].x + vals[i].y*vals[i].y
            + vals[i].z*vals[i].z + vals[i].w*vals[i].w;
    }
#pragma unroll
    for (int o = 16; o; o >>= 1) ss += __shfl_xor_sync(0xffffffffu, ss, o);
    float inv = 1.0f / fmaxf(sqrtf(ss), 1e-12f);
#pragma unroll
    for (int i = 0; i < 5; i++) {
        float4 v = vals[i];
        v.x *= inv; v.y *= inv; v.z *= inv; v.w *= inv;
        p[lane + i * 32] = v;
    }
}

// ---------------------------------------------------------------------------
// Sinkhorn prep: per-batch mask counts -> mu' (0 for masked rows); b init = 1.
// mask arrives as int32 (jax bool -> int32 per harness dtype set).
// ---------------------------------------------------------------------------
__global__ __launch_bounds__(1024) void prep(
    const int* __restrict__ mask,
    float* __restrict__ muP,
    float* __restrict__ bvec)
{
    const int b = blockIdx.x;
    const int m = threadIdx.x;
    int v = (mask[b * MM + m] != 0) ? 1 : 0;
    __shared__ int red[32];
    __shared__ int total;
    int s = v;
#pragma unroll
    for (int o = 16; o; o >>= 1) s += __shfl_xor_sync(0xffffffffu, s, o);
    if ((m & 31) == 0) red[m >> 5] = s;
    __syncthreads();
    if (m < 32) {
        int t = red[m];
#pragma unroll
        for (int o = 16; o; o >>= 1) t += __shfl_xor_sync(0xffffffffu, t, o);
        if (m == 0) total = t;
    }
    __syncthreads();
    int cnt = total;
    muP[b * MM + m]  = v ? (1.0f / (float)cnt + 1e-8f) : 0.0f;
    bvec[b * MM + m] = 1.0f;
}

// ---------------------------------------------------------------------------
// Sinkhorn row step: a[b,m] = muP / sum_n Kx[b,m,n]*b[n]  (skip masked rows)
// One warp per row; bvec cached in smem.
// ---------------------------------------------------------------------------
__global__ __launch_bounds__(256) void sink_row(
    const float* __restrict__ Kx,
    const float* __restrict__ muP,
    const float* __restrict__ bvec,
    float* __restrict__ a)
{
    __shared__ float bs[NQ];
    const int blk = blockIdx.x;     // 1024 blocks
    const int b   = blk >> 7;       // 128 blocks per batch
    const int m   = (blk & 127) * 8 + (threadIdx.x >> 5);
    const int lane = threadIdx.x & 31;
    ((float4*)bs)[threadIdx.x] = ((const float4*)(bvec + b * NQ))[threadIdx.x];
    __syncthreads();
    float mu = muP[b * MM + m];
    float av = 0.f;
    if (mu != 0.f) {
        const float4* row = (const float4*)(Kx + ((size_t)b * MM + m) * NQ);
        float s = 0.f;
#pragma unroll
        for (int i = 0; i < 8; i++) {
            float4 kv = row[lane + i * 32];
            float4 bv = ((const float4*)bs)[lane + i * 32];
            s += kv.x*bv.x + kv.y*bv.y + kv.z*bv.z + kv.w*bv.w;
        }
#pragma unroll
        for (int o = 16; o; o >>= 1) s += __shfl_xor_sync(0xffffffffu, s, o);
        av = mu / s;
    }
    if (lane == 0) a[b * MM + m] = av;
}

// ---------------------------------------------------------------------------
// Sinkhorn col step: b[b,n] = nuP / sum_m a[b,m]*Kx[b,m,n]  (a==0 rows skipped)
// Block covers 32 columns; 8 warp-groups stride over m.
// ---------------------------------------------------------------------------
__global__ __launch_bounds__(256) void sink_col(
    const float* __restrict__ Kx,
    const float* __restrict__ a,
    float* __restrict__ bvec,
    float nuP)
{
    __shared__ float as_[MM];
    __shared__ float part[8][32];
    const int b  = blockIdx.y;
    const int n0 = blockIdx.x * 32;
    ((float4*)as_)[threadIdx.x] = ((const float4*)(a + b * MM))[threadIdx.x];
    __syncthreads();
    const int col = threadIdx.x & 31;
    const int grp = threadIdx.x >> 5;
    const float* base = Kx + (size_t)b * MM * NQ + n0 + col;
    float s = 0.f;
#pragma unroll 4
    for (int m = grp; m < MM; m += 8) {
        float am = as_[m];
        if (am != 0.f) s += am * base[(size_t)m * NQ];
    }
    part[grp][col] = s;
    __syncthreads();
    if (threadIdx.x < 32) {
        float t = 0.f;
#pragma unroll
        for (int g = 0; g < 8; g++) t += part[g][col];
        bvec[b * NQ + n0 + col] = (t > 0.f) ? (nuP / t) : 0.f;
    }
}

// ---------------------------------------------------------------------------
// attn_save[b,m] = mask ? M*Nq * a[m] * sum_n sim*Kx*b[n] : 0
// ---------------------------------------------------------------------------
__global__ __launch_bounds__(256) void attn_kernel(
    const float* __restrict__ sim,
    const float* __restrict__ Kx,
    const float* __restrict__ a,
    const float* __restrict__ bvec,
    const float* __restrict__ muP,
    float* __restrict__ out_attn)
{
    __shared__ float bs[NQ];
    const int blk = blockIdx.x;
    const int b   = blk >> 7;
    const int m   = (blk & 127) * 8 + (threadIdx.x >> 5);
    const int lane = threadIdx.x & 31;
    ((float4*)bs)[threadIdx.x] = ((const float4*)(bvec + b * NQ))[threadIdx.x];
    __syncthreads();
    float mu  = muP[b * MM + m];
    float val = 0.f;
    if (mu != 0.f) {
        size_t off = ((size_t)b * MM + m) * NQ;
        const float4* srow = (const float4*)(sim + off);
        const float4* krow = (const float4*)(Kx + off);
        float s = 0.f;
#pragma unroll
        for (int i = 0; i < 8; i++) {
            float4 sv = srow[lane + i * 32];
            float4 kv = krow[lane + i * 32];
            float4 bv = ((const float4*)bs)[lane + i * 32];
            s += sv.x*kv.x*bv.x + sv.y*kv.y*bv.y + sv.z*kv.z*bv.z + sv.w*kv.w*bv.w;
        }
#pragma unroll
        for (int o = 16; o; o >>= 1) s += __shfl_xor_sync(0xffffffffu, s, o);
        val = (float)(MM) * (float)(NQ) * a[b * MM + m] * s;
    }
    if (lane == 0) out_attn[b * MM + m] = val;
}

// ---------------------------------------------------------------------------
extern "C" void kernel_launch(void* const* d_in, const int* in_sizes, int n_in,
                              void* d_out, int out_size)
{
    const float* xq = (const float*)d_in[0];
    const float* xk = (const float*)d_in[1];
    const float* xv = (const float*)d_in[2];
    const int*   mask = (const int*)d_in[3];   // bool -> int32 in harness
    const float* Wq = (const float*)d_in[4];
    const float* bq = (const float*)d_in[5];
    const float* Wk = (const float*)d_in[6];
    const float* bk = (const float*)d_in[7];
    const float* Wv = (const float*)d_in[8];
    const float* bv = (const float*)d_in[9];
    const float* Wp = (const float*)d_in[10];
    const float* bp = (const float*)d_in[11];

    float* out  = (float*)d_out;
    float* attn = out + (size_t)RR * CC;   // (8,1024) after the (1024,8,640) out

    float *q, *k, *v, *x, *sim, *Kx, *a, *b, *mu;
    cudaGetSymbolAddress((void**)&q,   g_q);
    cudaGetSymbolAddress((void**)&k,   g_k);
    cudaGetSymbolAddress((void**)&v,   g_v);
    cudaGetSymbolAddress((void**)&x,   g_x);
    cudaGetSymbolAddress((void**)&sim, g_sim);
    cudaGetSymbolAddress((void**)&Kx,  g_Kx);
    cudaGetSymbolAddress((void**)&a,   g_a);
    cudaGetSymbolAddress((void**)&b,   g_b);
    cudaGetSymbolAddress((void**)&mu,  g_mu);

    dim3 gP(CC / 128, RR / 128);   // (5, 64)

    gemm_proj<<<gP, 256>>>(xq, Wq, bq, q);
    gemm_proj<<<gP, 256>>>(xk, Wk, bk, k);
    gemm_proj<<<gP, 256>>>(xv, Wv, bv, v);
    l2norm_rows<<<RR / 8, 256>>>(q);
    l2norm_rows<<<RR / 8, 256>>>(k);
    prep<<<BB, 1024>>>(mask, mu, b);

    gemm_sim<<<dim3(NQ / 128, MM / 128, BB), 256>>>(k, q, sim, Kx);

    const float nuP = 1.0f / (float)NQ + 1e-8f;
    for (int it = 0; it < N_ITERS; it++) {
        sink_row<<<(BB * MM) / 8, 256>>>(Kx, mu, b, a);
        sink_col<<<dim3(NQ / 32, BB), 256>>>(Kx, a, b, nuP);
    }

    attn_kernel<<<(BB * MM) / 8, 256>>>(sim, Kx, a, b, mu, attn);
    gemm_x<<<dim3(CC / 128, NQ / 128, BB), 256>>>(Kx, v, a, b, x);
    gemm_proj<<<gP, 256>>>(x, Wp, bp, out);
}

// round 9
// speedup vs baseline: 1.4681x; 1.4681x over previous
#include <cuda_runtime.h>
#include <cuda_bf16.h>
#include <math.h>
#include <stdint.h>

// ---------------------------------------------------------------------------
//   xq: (1024, 8, 640)   xk/xv: (8, 1024, 640)   mask: (8, 1024) int32 (bool)
//   Wq/Wk/Wv/Wp: (640,640), biases (640)
//   out: (1024, 8, 640) fp32, attn_save: (8, 1024) fp32
// ---------------------------------------------------------------------------
#define NQ   1024
#define BB   8
#define MM   1024
#define CC   640
#define RR   (NQ * BB)
#define EPS_OT 0.05f
#define N_ITERS 100

#define AP   40     // smem pitch (bf16) for NT tiles, K-tile 32 + 8 pad
#define XAP  136    // gemm_x A tile pitch: n=128 + 8
#define XBP  72     // gemm_x B tile pitch: c=64 + 8

// ---------------- static device scratch (allocation-free rule) -------------
__device__ float g_q  [RR * CC];
__device__ float g_k  [RR * CC];
__device__ float g_v  [RR * CC];
__device__ float g_x  [RR * CC];
__device__ float g_sim[(size_t)BB * MM * NQ];
__device__ float g_Kx [(size_t)BB * MM * NQ];
__device__ float g_a  [BB * MM];
__device__ float g_b  [BB * NQ];
__device__ float g_mu [BB * MM];

// ---------------------------------------------------------------------------
// MMA / ldmatrix helpers
// ---------------------------------------------------------------------------
__device__ __forceinline__ uint32_t s2u(const void* p) {
    return (uint32_t)__cvta_generic_to_shared(p);
}
__device__ __forceinline__ void mma16816(float* d, const uint32_t* a, const uint32_t* b) {
    asm volatile(
        "mma.sync.aligned.m16n8k16.row.col.f32.bf16.bf16.f32 "
        "{%0,%1,%2,%3}, {%4,%5,%6,%7}, {%8,%9}, {%0,%1,%2,%3};\n"
        : "+f"(d[0]), "+f"(d[1]), "+f"(d[2]), "+f"(d[3])
        : "r"(a[0]), "r"(a[1]), "r"(a[2]), "r"(a[3]), "r"(b[0]), "r"(b[1]));
}
__device__ __forceinline__ void ldsm4(uint32_t* r, uint32_t a) {
    asm volatile("ldmatrix.sync.aligned.m8n8.x4.shared.b16 {%0,%1,%2,%3}, [%4];\n"
                 : "=r"(r[0]), "=r"(r[1]), "=r"(r[2]), "=r"(r[3]) : "r"(a));
}
__device__ __forceinline__ void ldsm2(uint32_t* r, uint32_t a) {
    asm volatile("ldmatrix.sync.aligned.m8n8.x2.shared.b16 {%0,%1}, [%2];\n"
                 : "=r"(r[0]), "=r"(r[1]) : "r"(a));
}
__device__ __forceinline__ void ldsm4t(uint32_t* r, uint32_t a) {
    asm volatile("ldmatrix.sync.aligned.m8n8.x4.trans.shared.b16 {%0,%1,%2,%3}, [%4];\n"
                 : "=r"(r[0]), "=r"(r[1]), "=r"(r[2]), "=r"(r[3]) : "r"(a));
}
__device__ __forceinline__ void ldsm2t(uint32_t* r, uint32_t a) {
    asm volatile("ldmatrix.sync.aligned.m8n8.x2.trans.shared.b16 {%0,%1}, [%2];\n"
                 : "=r"(r[0]), "=r"(r[1]) : "r"(a));
}
// fp32 -> bf16 hi + residual lo (hi+lo carries 16 mantissa bits; products exact)
__device__ __forceinline__ void split2(float f, __nv_bfloat16& h, __nv_bfloat16& l) {
    h = __float2bfloat16(f);
    l = __float2bfloat16(f - __bfloat162float(h));
}
__device__ __forceinline__ void store4(__nv_bfloat16* H, __nv_bfloat16* L, int base, float4 v) {
    __nv_bfloat16 h0,l0,h1,l1,h2,l2,h3,l3;
    split2(v.x,h0,l0); split2(v.y,h1,l1); split2(v.z,h2,l2); split2(v.w,h3,l3);
    __nv_bfloat162 a; a.x=h0; a.y=h1; __nv_bfloat162 b; b.x=h2; b.y=h3;
    __nv_bfloat162 c; c.x=l0; c.y=l1; __nv_bfloat162 d; d.x=l2; d.y=l3;
    *(__nv_bfloat162*)(H + base)     = a;
    *(__nv_bfloat162*)(H + base + 2) = b;
    *(__nv_bfloat162*)(L + base)     = c;
    *(__nv_bfloat162*)(L + base + 2) = d;
}

// NT mma phase over one BK=32 smem tile: A[128][32] x B[64][32] -> d[2][4][4]
__device__ __forceinline__ void mma_phase_nt(
    const __nv_bfloat16* Ah, const __nv_bfloat16* Al,
    const __nv_bfloat16* Bh, const __nv_bfloat16* Bl,
    int wm, int wn, int lane, float d[2][4][4])
{
#pragma unroll
    for (int ks = 0; ks < 32; ks += 16) {
        uint32_t ah[2][4], al[2][4], bh[4][2], bl[4][2];
#pragma unroll
        for (int i = 0; i < 2; i++) {
            int row = wm + i * 16 + (lane & 15);
            int col = ks + (lane >> 4) * 8;
            uint32_t off = (uint32_t)(row * AP + col) * 2;
            ldsm4(ah[i], s2u(Ah) + off);
            ldsm4(al[i], s2u(Al) + off);
        }
#pragma unroll
        for (int j = 0; j < 4; j++) {
            int row = wn + j * 8 + (lane & 7);
            int col = ks + ((lane >> 3) & 1) * 8;
            uint32_t off = (uint32_t)(row * AP + col) * 2;
            ldsm2(bh[j], s2u(Bh) + off);
            ldsm2(bl[j], s2u(Bl) + off);
        }
#pragma unroll
        for (int i = 0; i < 2; i++)
#pragma unroll
            for (int j = 0; j < 4; j++) {
                mma16816(d[i][j], ah[i], bh[j]);
                mma16816(d[i][j], ah[i], bl[j]);
                mma16816(d[i][j], al[i], bh[j]);
            }
    }
}

// ---------------------------------------------------------------------------
// Projection GEMM via tensor cores:
// out[r,j] = sum_c A[r,c] * W[j,c] + bias[j]    (M=8192, N=640, K=640)
// ---------------------------------------------------------------------------
__global__ __launch_bounds__(256) void gemm_proj_tc(
    const float* __restrict__ A, const float* __restrict__ W,
    const float* __restrict__ bias, float* __restrict__ out)
{
    __shared__ __nv_bfloat16 Ah[128 * AP], Al[128 * AP];
    __shared__ __nv_bfloat16 Bh[64 * AP],  Bl[64 * AP];
    const int tid = threadIdx.x;
    const int m0 = blockIdx.y * 128, n0 = blockIdx.x * 64;
    const int lane = tid & 31, warp = tid >> 5;
    const int wm = (warp & 3) * 32, wn = (warp >> 2) * 32;

    float d[2][4][4];
#pragma unroll
    for (int i = 0; i < 2; i++)
#pragma unroll
        for (int j = 0; j < 4; j++)
#pragma unroll
            for (int e = 0; e < 4; e++) d[i][j][e] = 0.f;

    const int ar = tid >> 1, ak = (tid & 1) * 16;
    const int br = tid >> 2, bk = (tid & 3) * 8;
    const float* Ap = A + (size_t)(m0 + ar) * CC + ak;
    const float* Bp = W + (size_t)(n0 + br) * CC + bk;

    for (int k0 = 0; k0 < CC; k0 += 32) {
#pragma unroll
        for (int i = 0; i < 4; i++)
            store4(Ah, Al, ar * AP + ak + i * 4, *(const float4*)(Ap + k0 + i * 4));
#pragma unroll
        for (int i = 0; i < 2; i++)
            store4(Bh, Bl, br * AP + bk + i * 4, *(const float4*)(Bp + k0 + i * 4));
        __syncthreads();
        mma_phase_nt(Ah, Al, Bh, Bl, wm, wn, lane, d);
        __syncthreads();
    }

#pragma unroll
    for (int i = 0; i < 2; i++) {
        int r0 = m0 + wm + i * 16 + (lane >> 2);
#pragma unroll
        for (int j = 0; j < 4; j++) {
            int c = n0 + wn + j * 8 + (lane & 3) * 2;
            float2 bi = *(const float2*)(bias + c);
            float2 o0 = { d[i][j][0] + bi.x, d[i][j][1] + bi.y };
            float2 o1 = { d[i][j][2] + bi.x, d[i][j][3] + bi.y };
            *(float2*)(out + (size_t)r0 * CC + c)       = o0;
            *(float2*)(out + (size_t)(r0 + 8) * CC + c) = o1;
        }
    }
}

// ---------------------------------------------------------------------------
// sim GEMM: sim[b,m,n] = sum_c k[b,m,c]*q[n,b,c];  Kx = exp((sim-1)/eps)
// ---------------------------------------------------------------------------
__global__ __launch_bounds__(256) void gemm_sim_tc(
    const float* __restrict__ kb, const float* __restrict__ qb,
    float* __restrict__ sim, float* __restrict__ Kx)
{
    __shared__ __nv_bfloat16 Ah[128 * AP], Al[128 * AP];
    __shared__ __nv_bfloat16 Bh[64 * AP],  Bl[64 * AP];
    const int b = blockIdx.z;
    const int tid = threadIdx.x;
    const int m0 = blockIdx.y * 128, n0 = blockIdx.x * 64;
    const int lane = tid & 31, warp = tid >> 5;
    const int wm = (warp & 3) * 32, wn = (warp >> 2) * 32;

    float d[2][4][4];
#pragma unroll
    for (int i = 0; i < 2; i++)
#pragma unroll
        for (int j = 0; j < 4; j++)
#pragma unroll
            for (int e = 0; e < 4; e++) d[i][j][e] = 0.f;

    const int ar = tid >> 1, ak = (tid & 1) * 16;
    const int br = tid >> 2, bk = (tid & 3) * 8;
    const float* Ap = kb + ((size_t)b * MM + m0 + ar) * CC + ak;
    const float* Bp = qb + (size_t)(n0 + br) * (BB * CC) + (size_t)b * CC + bk;

    for (int k0 = 0; k0 < CC; k0 += 32) {
#pragma unroll
        for (int i = 0; i < 4; i++)
            store4(Ah, Al, ar * AP + ak + i * 4, *(const float4*)(Ap + k0 + i * 4));
#pragma unroll
        for (int i = 0; i < 2; i++)
            store4(Bh, Bl, br * AP + bk + i * 4, *(const float4*)(Bp + k0 + i * 4));
        __syncthreads();
        mma_phase_nt(Ah, Al, Bh, Bl, wm, wn, lane, d);
        __syncthreads();
    }

#pragma unroll
    for (int i = 0; i < 2; i++) {
        int m = m0 + wm + i * 16 + (lane >> 2);
#pragma unroll
        for (int j = 0; j < 4; j++) {
            int n = n0 + wn + j * 8 + (lane & 3) * 2;
            size_t o0 = ((size_t)b * MM + m) * NQ + n;
            size_t o1 = ((size_t)b * MM + m + 8) * NQ + n;
            float2 s0 = { d[i][j][0], d[i][j][1] };
            float2 s1 = { d[i][j][2], d[i][j][3] };
            *(float2*)(sim + o0) = s0;
            *(float2*)(sim + o1) = s1;
            float2 k0v = { expf((s0.x - 1.0f) / EPS_OT), expf((s0.y - 1.0f) / EPS_OT) };
            float2 k1v = { expf((s1.x - 1.0f) / EPS_OT), expf((s1.y - 1.0f) / EPS_OT) };
            *(float2*)(Kx + o0) = k0v;
            *(float2*)(Kx + o1) = k1v;
        }
    }
}

// ---------------------------------------------------------------------------
// x GEMM: x[n,b,c] = b[n] * sum_m (a[m]*Kx[b,m,n]) * v[b,m,c]
// Reduction over m; operands m-major in smem, fragments via ldmatrix.trans.
// ---------------------------------------------------------------------------
__global__ __launch_bounds__(256) void gemm_x_tc(
    const float* __restrict__ Kx, const float* __restrict__ v,
    const float* __restrict__ a, const float* __restrict__ bvec,
    float* __restrict__ x)
{
    __shared__ __nv_bfloat16 Ah[32 * XAP], Al[32 * XAP];   // [m][n] natural
    __shared__ __nv_bfloat16 Bh[32 * XBP], Bl[32 * XBP];   // [m][c] natural
    const int b = blockIdx.z;
    const int tid = threadIdx.x;
    const int n0 = blockIdx.y * 128, c0 = blockIdx.x * 64;
    const int lane = tid & 31, warp = tid >> 5;
    const int wm = (warp & 3) * 32, wn = (warp >> 2) * 32;

    float d[2][4][4];
#pragma unroll
    for (int i = 0; i < 2; i++)
#pragma unroll
        for (int j = 0; j < 4; j++)
#pragma unroll
            for (int e = 0; e < 4; e++) d[i][j][e] = 0.f;

    const int amm = tid >> 3, ann = (tid & 7) * 16;   // A: 32 m-rows x 128 n
    const int bmm = tid >> 3, bcc = (tid & 7) * 8;    // B: 32 m-rows x 64 c

    for (int m0k = 0; m0k < MM; m0k += 32) {
        float am = a[b * MM + m0k + amm];
        const float* Ap = Kx + ((size_t)b * MM + m0k + amm) * NQ + n0 + ann;
        const float* Bp = v  + ((size_t)b * MM + m0k + bmm) * CC + c0 + bcc;
#pragma unroll
        for (int i = 0; i < 4; i++) {
            float4 vv = *(const float4*)(Ap + i * 4);
            vv.x *= am; vv.y *= am; vv.z *= am; vv.w *= am;
            store4(Ah, Al, amm * XAP + ann + i * 4, vv);
        }
#pragma unroll
        for (int i = 0; i < 2; i++)
            store4(Bh, Bl, bmm * XBP + bcc + i * 4, *(const float4*)(Bp + i * 4));
        __syncthreads();

#pragma unroll
        for (int ks = 0; ks < 32; ks += 16) {
            uint32_t ah[2][4], al[2][4], bh[4][2], bl[4][2];
#pragma unroll
            for (int i = 0; i < 2; i++) {
                int row = ks + (lane & 7) + ((lane >> 4) << 3);
                int col = wm + i * 16 + ((lane >> 3) & 1) * 8;
                uint32_t off = (uint32_t)(row * XAP + col) * 2;
                ldsm4t(ah[i], s2u(Ah) + off);
                ldsm4t(al[i], s2u(Al) + off);
            }
#pragma unroll
            for (int j = 0; j < 4; j++) {
                int row = ks + (lane & 15);
                int col = wn + j * 8;
                uint32_t off = (uint32_t)(row * XBP + col) * 2;
                ldsm2t(bh[j], s2u(Bh) + off);
                ldsm2t(bl[j], s2u(Bl) + off);
            }
#pragma unroll
            for (int i = 0; i < 2; i++)
#pragma unroll
                for (int j = 0; j < 4; j++) {
                    mma16816(d[i][j], ah[i], bh[j]);
                    mma16816(d[i][j], ah[i], bl[j]);
                    mma16816(d[i][j], al[i], bh[j]);
                }
        }
        __syncthreads();
    }

#pragma unroll
    for (int i = 0; i < 2; i++) {
        int n = n0 + wm + i * 16 + (lane >> 2);
        float bn0 = bvec[b * NQ + n];
        float bn1 = bvec[b * NQ + n + 8];
#pragma unroll
        for (int j = 0; j < 4; j++) {
            int c = c0 + wn + j * 8 + (lane & 3) * 2;
            float2 o0 = { d[i][j][0] * bn0, d[i][j][1] * bn0 };
            float2 o1 = { d[i][j][2] * bn1, d[i][j][3] * bn1 };
            *(float2*)(x + ((size_t)n * BB + b) * CC + c)       = o0;
            *(float2*)(x + ((size_t)(n + 8) * BB + b) * CC + c) = o1;
        }
    }
}

// ---------------------------------------------------------------------------
// l2norm over each 640-element row, in place. One warp per row.
// ---------------------------------------------------------------------------
__global__ __launch_bounds__(256) void l2norm_rows(float* __restrict__ buf)
{
    const int row  = blockIdx.x * 8 + (threadIdx.x >> 5);
    const int lane = threadIdx.x & 31;
    float4* p = (float4*)(buf + (size_t)row * CC);
    float4 vals[5];
    float ss = 0.f;
#pragma unroll
    for (int i = 0; i < 5; i++) {
        vals[i] = p[lane + i * 32];
        ss += vals[i].x*vals[i].x + vals[i].y*vals[i].y
            + vals[i].z*vals[i].z + vals[i].w*vals[i].w;
    }
#pragma unroll
    for (int o = 16; o; o >>= 1) ss += __shfl_xor_sync(0xffffffffu, ss, o);
    float inv = 1.0f / fmaxf(sqrtf(ss), 1e-12f);
#pragma unroll
    for (int i = 0; i < 5; i++) {
        float4 v = vals[i];
        v.x *= inv; v.y *= inv; v.z *= inv; v.w *= inv;
        p[lane + i * 32] = v;
    }
}

// ---------------------------------------------------------------------------
// Sinkhorn prep (mask = int32)
// ---------------------------------------------------------------------------
__global__ __launch_bounds__(1024) void prep(
    const int* __restrict__ mask,
    float* __restrict__ muP,
    float* __restrict__ bvec)
{
    const int b = blockIdx.x;
    const int m = threadIdx.x;
    int v = (mask[b * MM + m] != 0) ? 1 : 0;
    __shared__ int red[32];
    __shared__ int total;
    int s = v;
#pragma unroll
    for (int o = 16; o; o >>= 1) s += __shfl_xor_sync(0xffffffffu, s, o);
    if ((m & 31) == 0) red[m >> 5] = s;
    __syncthreads();
    if (m < 32) {
        int t = red[m];
#pragma unroll
        for (int o = 16; o; o >>= 1) t += __shfl_xor_sync(0xffffffffu, t, o);
        if (m == 0) total = t;
    }
    __syncthreads();
    int cnt = total;
    muP[b * MM + m]  = v ? (1.0f / (float)cnt + 1e-8f) : 0.0f;
    bvec[b * MM + m] = 1.0f;
}

// ---------------------------------------------------------------------------
// Sinkhorn row step: a[b,m] = muP / sum_n Kx[b,m,n]*b[n]
// ---------------------------------------------------------------------------
__global__ __launch_bounds__(256) void sink_row(
    const float* __restrict__ Kx,
    const float* __restrict__ muP,
    const float* __restrict__ bvec,
    float* __restrict__ a)
{
    __shared__ float bs[NQ];
    const int blk = blockIdx.x;
    const int b   = blk >> 7;
    const int m   = (blk & 127) * 8 + (threadIdx.x >> 5);
    const int lane = threadIdx.x & 31;
    ((float4*)bs)[threadIdx.x] = ((const float4*)(bvec + b * NQ))[threadIdx.x];
    __syncthreads();
    float mu = muP[b * MM + m];
    float av = 0.f;
    if (mu != 0.f) {
        const float4* row = (const float4*)(Kx + ((size_t)b * MM + m) * NQ);
        float s = 0.f;
#pragma unroll
        for (int i = 0; i < 8; i++) {
            float4 kv = row[lane + i * 32];
            float4 bv = ((const float4*)bs)[lane + i * 32];
            s += kv.x*bv.x + kv.y*bv.y + kv.z*bv.z + kv.w*bv.w;
        }
#pragma unroll
        for (int o = 16; o; o >>= 1) s += __shfl_xor_sync(0xffffffffu, s, o);
        av = mu / s;
    }
    if (lane == 0) a[b * MM + m] = av;
}

// ---------------------------------------------------------------------------
// Sinkhorn col step: b[b,n] = nuP / sum_m a[b,m]*Kx[b,m,n]
// ---------------------------------------------------------------------------
__global__ __launch_bounds__(256) void sink_col(
    const float* __restrict__ Kx,
    const float* __restrict__ a,
    float* __restrict__ bvec,
    float nuP)
{
    __shared__ float as_[MM];
    __shared__ float part[8][32];
    const int b  = blockIdx.y;
    const int n0 = blockIdx.x * 32;
    ((float4*)as_)[threadIdx.x] = ((const float4*)(a + b * MM))[threadIdx.x];
    __syncthreads();
    const int col = threadIdx.x & 31;
    const int grp = threadIdx.x >> 5;
    const float* base = Kx + (size_t)b * MM * NQ + n0 + col;
    float s = 0.f;
#pragma unroll 4
    for (int m = grp; m < MM; m += 8) {
        float am = as_[m];
        if (am != 0.f) s += am * base[(size_t)m * NQ];
    }
    part[grp][col] = s;
    __syncthreads();
    if (threadIdx.x < 32) {
        float t = 0.f;
#pragma unroll
        for (int g = 0; g < 8; g++) t += part[g][col];
        bvec[b * NQ + n0 + col] = (t > 0.f) ? (nuP / t) : 0.f;
    }
}

// ---------------------------------------------------------------------------
// attn_save[b,m] = mask ? M*Nq * a[m] * sum_n sim*Kx*b[n] : 0
// ---------------------------------------------------------------------------
__global__ __launch_bounds__(256) void attn_kernel(
    const float* __restrict__ sim,
    const float* __restrict__ Kx,
    const float* __restrict__ a,
    const float* __restrict__ bvec,
    const float* __restrict__ muP,
    float* __restrict__ out_attn)
{
    __shared__ float bs[NQ];
    const int blk = blockIdx.x;
    const int b   = blk >> 7;
    const int m   = (blk & 127) * 8 + (threadIdx.x >> 5);
    const int lane = threadIdx.x & 31;
    ((float4*)bs)[threadIdx.x] = ((const float4*)(bvec + b * NQ))[threadIdx.x];
    __syncthreads();
    float mu  = muP[b * MM + m];
    float val = 0.f;
    if (mu != 0.f) {
        size_t off = ((size_t)b * MM + m) * NQ;
        const float4* srow = (const float4*)(sim + off);
        const float4* krow = (const float4*)(Kx + off);
        float s = 0.f;
#pragma unroll
        for (int i = 0; i < 8; i++) {
            float4 sv = srow[lane + i * 32];
            float4 kv = krow[lane + i * 32];
            float4 bv = ((const float4*)bs)[lane + i * 32];
            s += sv.x*kv.x*bv.x + sv.y*kv.y*bv.y + sv.z*kv.z*bv.z + sv.w*kv.w*bv.w;
        }
#pragma unroll
        for (int o = 16; o; o >>= 1) s += __shfl_xor_sync(0xffffffffu, s, o);
        val = (float)(MM) * (float)(NQ) * a[b * MM + m] * s;
    }
    if (lane == 0) out_attn[b * MM + m] = val;
}

// ---------------------------------------------------------------------------
extern "C" void kernel_launch(void* const* d_in, const int* in_sizes, int n_in,
                              void* d_out, int out_size)
{
    const float* xq = (const float*)d_in[0];
    const float* xk = (const float*)d_in[1];
    const float* xv = (const float*)d_in[2];
    const int*   mask = (const int*)d_in[3];
    const float* Wq = (const float*)d_in[4];
    const float* bq = (const float*)d_in[5];
    const float* Wk = (const float*)d_in[6];
    const float* bk = (const float*)d_in[7];
    const float* Wv = (const float*)d_in[8];
    const float* bv = (const float*)d_in[9];
    const float* Wp = (const float*)d_in[10];
    const float* bp = (const float*)d_in[11];

    float* out  = (float*)d_out;
    float* attn = out + (size_t)RR * CC;

    float *q, *k, *v, *x, *sim, *Kx, *a, *b, *mu;
    cudaGetSymbolAddress((void**)&q,   g_q);
    cudaGetSymbolAddress((void**)&k,   g_k);
    cudaGetSymbolAddress((void**)&v,   g_v);
    cudaGetSymbolAddress((void**)&x,   g_x);
    cudaGetSymbolAddress((void**)&sim, g_sim);
    cudaGetSymbolAddress((void**)&Kx,  g_Kx);
    cudaGetSymbolAddress((void**)&a,   g_a);
    cudaGetSymbolAddress((void**)&b,   g_b);
    cudaGetSymbolAddress((void**)&mu,  g_mu);

    dim3 gP(CC / 64, RR / 128);   // (10, 64)

    gemm_proj_tc<<<gP, 256>>>(xq, Wq, bq, q);
    gemm_proj_tc<<<gP, 256>>>(xk, Wk, bk, k);
    gemm_proj_tc<<<gP, 256>>>(xv, Wv, bv, v);
    l2norm_rows<<<RR / 8, 256>>>(q);
    l2norm_rows<<<RR / 8, 256>>>(k);
    prep<<<BB, 1024>>>(mask, mu, b);

    gemm_sim_tc<<<dim3(NQ / 64, MM / 128, BB), 256>>>(k, q, sim, Kx);

    const float nuP = 1.0f / (float)NQ + 1e-8f;
    for (int it = 0; it < N_ITERS; it++) {
        sink_row<<<(BB * MM) / 8, 256>>>(Kx, mu, b, a);
        sink_col<<<dim3(NQ / 32, BB), 256>>>(Kx, a, b, nuP);
    }

    attn_kernel<<<(BB * MM) / 8, 256>>>(sim, Kx, a, b, mu, attn);
    gemm_x_tc<<<dim3(CC / 64, NQ / 128, BB), 256>>>(Kx, v, a, b, x);
    gemm_proj_tc<<<gP, 256>>>(x, Wp, bp, out);
}